// round 15
// baseline (speedup 1.0000x reference)
#include <cuda_runtime.h>
#include <cuda_bf16.h>

// Problem shape (fixed by the reference)
#define BB 16
#define TT 4096
#define HH 512
#define SS 64            // T-chunks per batch
#define TC (TT / SS)     // 64 rows per chunk
#define H4 (HH / 4)      // 128 float4 per row
#define GRP 8            // chunks per reduction group
#define NG (SS / GRP)    // 8 groups per batch

// Scratch. All mutated state is reset by the finalizer -> graph-replayable.
__device__ float g_partial[BB * SS * 2 * HH];   // 4 MiB unique partials (STG)
__device__ int   g_counts[BB * SS];
__device__ float g_final[BB][2 * HH];           // 128 KB, REDG-accumulated
__device__ int   g_cntf[BB];
__device__ int   g_gdone[BB * NG];
__device__ int   g_done[BB];

// Single kernel: CTA = (b, contiguous t-chunk). R14's batched MLP stream,
// then hierarchical epilogue: 8th arriver per group reduces the group's
// L2-hot partials into g_final (128K REDG lanes total); last group per
// batch divides and writes out.
__global__ __launch_bounds__(128) void pool_kernel(
    const float4* __restrict__ x,
    const int* __restrict__ lengths,
    const int* __restrict__ mask,        // jax bool materialized as int32
    float* __restrict__ out)
{
    const int blk = blockIdx.x;          // 0 .. B*SS-1
    const int b   = blk / SS;
    const int s   = blk % SS;
    const int tid = threadIdx.x;         // 0..127

    const int L  = lengths[b];
    const int t0 = s * TC;
    int Lc = L - t0;
    Lc = Lc < 0 ? 0 : (Lc > TC ? TC : Lc);

    const float4* __restrict__ xp = x + (size_t)b * TT * H4 + (size_t)t0 * H4 + tid;
    const int* __restrict__ mp = mask + (size_t)b * TT + t0;   // 256B-aligned

    float4 ag = make_float4(0.f, 0.f, 0.f, 0.f);
    float4 al = make_float4(0.f, 0.f, 0.f, 0.f);
    int cnt = 0;

    // ---- Region A: t < Lc. 4-row batches, branch-free accumulation. ----
    const int LcA = Lc & ~3;
    int t = 0;
    #pragma unroll 2
    for (; t < LcA; t += 4) {
        const float4 v0 = xp[(size_t)(t + 0) * H4];
        const float4 v1 = xp[(size_t)(t + 1) * H4];
        const float4 v2 = xp[(size_t)(t + 2) * H4];
        const float4 v3 = xp[(size_t)(t + 3) * H4];
        const int4 mm = *reinterpret_cast<const int4*>(mp + t);

        ag.x += (v0.x + v1.x) + (v2.x + v3.x);
        ag.y += (v0.y + v1.y) + (v2.y + v3.y);
        ag.z += (v0.z + v1.z) + (v2.z + v3.z);
        ag.w += (v0.w + v1.w) + (v2.w + v3.w);

        const float w0 = mm.x ? 1.f : 0.f;
        const float w1 = mm.y ? 1.f : 0.f;
        const float w2 = mm.z ? 1.f : 0.f;
        const float w3 = mm.w ? 1.f : 0.f;
        al.x = fmaf(w0, v0.x, fmaf(w1, v1.x, fmaf(w2, v2.x, fmaf(w3, v3.x, al.x))));
        al.y = fmaf(w0, v0.y, fmaf(w1, v1.y, fmaf(w2, v2.y, fmaf(w3, v3.y, al.y))));
        al.z = fmaf(w0, v0.z, fmaf(w1, v1.z, fmaf(w2, v2.z, fmaf(w3, v3.z, al.z))));
        al.w = fmaf(w0, v0.w, fmaf(w1, v1.w, fmaf(w2, v2.w, fmaf(w3, v3.w, al.w))));
        cnt += (mm.x ? 1 : 0) + (mm.y ? 1 : 0) + (mm.z ? 1 : 0) + (mm.w ? 1 : 0);
    }
    for (; t < Lc; ++t) {                // remainder (0-3 rows)
        float4 v = xp[(size_t)t * H4];
        ag.x += v.x; ag.y += v.y; ag.z += v.z; ag.w += v.w;
        if (mp[t] != 0) { al.x += v.x; al.y += v.y; al.z += v.z; al.w += v.w; cnt++; }
    }
    // ---- Region B: t >= Lc — fetch only masked rows (uniform skip). ----
    #pragma unroll 4
    for (; t < TC; ++t) {
        if (mp[t] != 0) {
            float4 v = xp[(size_t)t * H4];
            al.x += v.x; al.y += v.y; al.z += v.z; al.w += v.w; cnt++;
        }
    }

    // Publish unique partial (plain stores, proven cheap).
    float4* outp = reinterpret_cast<float4*>(g_partial) + (size_t)blk * (2 * HH / 4);
    outp[tid]      = ag;
    outp[H4 + tid] = al;
    if (tid == 0) g_counts[blk] = cnt;

    // ---- group-of-8 reduce: 8th arriver handles its group (L2-hot). ----
    __shared__ int sv;
    __threadfence();
    __syncthreads();
    if (tid == 0) sv = atomicAdd(&g_gdone[b * NG + (s >> 3)], 1);
    __syncthreads();
    if (sv != GRP - 1) return;

    __threadfence();                     // acquire group-mates' partials
    const int blk0 = b * SS + (s & ~(GRP - 1));
    #pragma unroll
    for (int k2 = 0; k2 < 2; ++k2) {
        const int fc = k2 * 128 + tid;   // float4 column in [0, 256)
        float4 sum = make_float4(0.f, 0.f, 0.f, 0.f);
        #pragma unroll
        for (int c = 0; c < GRP; ++c) {
            float4 v = reinterpret_cast<const float4*>(g_partial)
                           [(size_t)(blk0 + c) * (2 * HH / 4) + fc];
            sum.x += v.x; sum.y += v.y; sum.z += v.z; sum.w += v.w;
        }
        float* gf = &g_final[b][0] + 4 * fc;
        atomicAdd(gf + 0, sum.x);
        atomicAdd(gf + 1, sum.y);
        atomicAdd(gf + 2, sum.z);
        atomicAdd(gf + 3, sum.w);
    }
    if (tid == 0) {
        int c8 = 0;
        #pragma unroll
        for (int c = 0; c < GRP; ++c) c8 += g_counts[blk0 + c];
        atomicAdd(&g_cntf[b], c8);
    }

    // ---- last group of this batch: finalize. ----
    __threadfence();
    __syncthreads();
    if (tid == 0) sv = atomicAdd(&g_done[b], 1);
    __syncthreads();
    if (sv != NG - 1) return;

    __threadfence();
    const int tot = g_cntf[b];
    const float dg = 1.0f / (float)(L   > 1 ? L   : 1);
    const float dl = 1.0f / (float)(tot > 1 ? tot : 1);

    float4* o4 = reinterpret_cast<float4*>(out) + (size_t)b * (2 * HH / 4);
    #pragma unroll
    for (int k2 = 0; k2 < 2; ++k2) {
        const int fc = k2 * 128 + tid;
        float4 v = reinterpret_cast<float4*>(&g_final[b][0])[fc];
        const float inv = (fc < H4) ? dg : dl;
        o4[fc] = make_float4(v.x * inv, v.y * inv, v.z * inv, v.w * inv);
        reinterpret_cast<float4*>(&g_final[b][0])[fc] =
            make_float4(0.f, 0.f, 0.f, 0.f);
    }
    if (tid == 0) { g_cntf[b] = 0; g_done[b] = 0; }
    if (tid < NG) g_gdone[b * NG + tid] = 0;
}

extern "C" void kernel_launch(void* const* d_in, const int* in_sizes, int n_in,
                              void* d_out, int out_size)
{
    const float4* x       = (const float4*)d_in[0];   // [B,T,H] f32
    const int*    lengths = (const int*)d_in[1];      // [B] i32
    const int*    mask    = (const int*)d_in[2];      // [B,T] bool -> i32
    float*        out     = (float*)d_out;            // [B, 2H] f32

    pool_kernel<<<BB * SS, 128>>>(x, lengths, mask, out);
}

// round 16
// speedup vs baseline: 1.0111x; 1.0111x over previous
#include <cuda_runtime.h>
#include <cuda_bf16.h>
#include <cooperative_groups.h>

namespace cg = cooperative_groups;

// Problem shape (fixed by the reference)
#define BB 16
#define TT 4096
#define HH 512
#define SS 64            // T-chunks per batch
#define TC (TT / SS)     // 64 rows per chunk
#define H4 (HH / 4)      // 128 float4 per row
#define NF4 (2 * HH / 4) // 256 float4 columns per batch

// Scratch: per (b, chunk): 512 global-sum + 512 local-sum floats (4 MiB).
// Fully overwritten every launch -> no reset needed, graph-replayable.
__device__ float g_partial[BB * SS * 2 * HH];
__device__ int   g_counts[BB * SS];

// Cooperative kernel: R14's batched stream, grid.sync(), then the same CTAs
// reduce the (still L2-hot) partials. No atomics, no flags, deterministic.
__global__ __launch_bounds__(128, 8) void pool_kernel(
    const float4* __restrict__ x,
    const int* __restrict__ lengths,
    const int* __restrict__ mask,        // jax bool materialized as int32
    float* __restrict__ out)
{
    const int blk = blockIdx.x;          // 0 .. B*SS-1
    const int b   = blk / SS;
    const int s   = blk % SS;
    const int tid = threadIdx.x;         // 0..127

    const int L  = lengths[b];
    const int t0 = s * TC;
    int Lc = L - t0;
    Lc = Lc < 0 ? 0 : (Lc > TC ? TC : Lc);

    const float4* __restrict__ xp = x + (size_t)b * TT * H4 + (size_t)t0 * H4 + tid;
    const int* __restrict__ mp = mask + (size_t)b * TT + t0;   // 256B-aligned

    float4 ag = make_float4(0.f, 0.f, 0.f, 0.f);
    float4 al = make_float4(0.f, 0.f, 0.f, 0.f);
    int cnt = 0;

    // ---- Region A: t < Lc. 4-row batches, branch-free accumulation. ----
    const int LcA = Lc & ~3;
    int t = 0;
    #pragma unroll 2
    for (; t < LcA; t += 4) {
        const float4 v0 = xp[(size_t)(t + 0) * H4];
        const float4 v1 = xp[(size_t)(t + 1) * H4];
        const float4 v2 = xp[(size_t)(t + 2) * H4];
        const float4 v3 = xp[(size_t)(t + 3) * H4];
        const int4 mm = *reinterpret_cast<const int4*>(mp + t);

        ag.x += (v0.x + v1.x) + (v2.x + v3.x);
        ag.y += (v0.y + v1.y) + (v2.y + v3.y);
        ag.z += (v0.z + v1.z) + (v2.z + v3.z);
        ag.w += (v0.w + v1.w) + (v2.w + v3.w);

        const float w0 = mm.x ? 1.f : 0.f;
        const float w1 = mm.y ? 1.f : 0.f;
        const float w2 = mm.z ? 1.f : 0.f;
        const float w3 = mm.w ? 1.f : 0.f;
        al.x = fmaf(w0, v0.x, fmaf(w1, v1.x, fmaf(w2, v2.x, fmaf(w3, v3.x, al.x))));
        al.y = fmaf(w0, v0.y, fmaf(w1, v1.y, fmaf(w2, v2.y, fmaf(w3, v3.y, al.y))));
        al.z = fmaf(w0, v0.z, fmaf(w1, v1.z, fmaf(w2, v2.z, fmaf(w3, v3.z, al.z))));
        al.w = fmaf(w0, v0.w, fmaf(w1, v1.w, fmaf(w2, v2.w, fmaf(w3, v3.w, al.w))));
        cnt += (mm.x ? 1 : 0) + (mm.y ? 1 : 0) + (mm.z ? 1 : 0) + (mm.w ? 1 : 0);
    }
    for (; t < Lc; ++t) {                // remainder (0-3 rows)
        float4 v = xp[(size_t)t * H4];
        ag.x += v.x; ag.y += v.y; ag.z += v.z; ag.w += v.w;
        if (mp[t] != 0) { al.x += v.x; al.y += v.y; al.z += v.z; al.w += v.w; cnt++; }
    }
    // ---- Region B: t >= Lc — fetch only masked rows (uniform skip). ----
    #pragma unroll 4
    for (; t < TC; ++t) {
        if (mp[t] != 0) {
            float4 v = xp[(size_t)t * H4];
            al.x += v.x; al.y += v.y; al.z += v.z; al.w += v.w; cnt++;
        }
    }

    // Publish unique partial (plain stores; stays in L2 until the sync).
    float4* outp = reinterpret_cast<float4*>(g_partial) + (size_t)blk * NF4;
    outp[tid]      = ag;
    outp[H4 + tid] = al;
    if (tid == 0) g_counts[blk] = cnt;

    // ---- grid-wide barrier: all partials written and visible. ----
    __threadfence();
    cg::this_grid().sync();

    // ---- Phase 2: same CTAs reduce the L2-hot partials. ----
    // CTA (b2, idx): 4 float4 columns fc = idx*4 + w (one per warp).
    // Lane l reduces chunks l and l+32; butterfly shuffle to lane 0.
    const int b2  = blk >> 6;            // blk / SS
    const int idx = blk & (SS - 1);
    const int w   = tid >> 5;            // warp 0..3
    const int l   = tid & 31;
    const int fc  = (idx << 2) + w;      // float4 column in [0, 256)

    const float4* pb = reinterpret_cast<const float4*>(g_partial)
                     + (size_t)b2 * SS * NF4 + fc;
    float4 a0 = pb[(size_t)l * NF4];
    float4 a1 = pb[(size_t)(l + 32) * NF4];
    float4 sum = make_float4(a0.x + a1.x, a0.y + a1.y, a0.z + a1.z, a0.w + a1.w);

    #pragma unroll
    for (int d = 16; d >= 1; d >>= 1) {
        sum.x += __shfl_xor_sync(0xffffffffu, sum.x, d);
        sum.y += __shfl_xor_sync(0xffffffffu, sum.y, d);
        sum.z += __shfl_xor_sync(0xffffffffu, sum.z, d);
        sum.w += __shfl_xor_sync(0xffffffffu, sum.w, d);
    }

    float inv;
    if (fc < H4) {                       // global half: denom = max(L, 1)
        const int Lb = lengths[b2];
        inv = 1.0f / (float)(Lb > 1 ? Lb : 1);
    } else {                             // local half: denom = max(cnt, 1)
        int c = g_counts[b2 * SS + l] + g_counts[b2 * SS + 32 + l];
        #pragma unroll
        for (int d = 16; d >= 1; d >>= 1)
            c += __shfl_xor_sync(0xffffffffu, c, d);
        inv = 1.0f / (float)(c > 1 ? c : 1);
    }

    if (l == 0) {
        reinterpret_cast<float4*>(out)[(size_t)b2 * NF4 + fc] =
            make_float4(sum.x * inv, sum.y * inv, sum.z * inv, sum.w * inv);
    }
}

extern "C" void kernel_launch(void* const* d_in, const int* in_sizes, int n_in,
                              void* d_out, int out_size)
{
    const float4* x       = (const float4*)d_in[0];   // [B,T,H] f32
    const int*    lengths = (const int*)d_in[1];      // [B] i32
    const int*    mask    = (const int*)d_in[2];      // [B,T] bool -> i32
    float*        out     = (float*)d_out;            // [B, 2H] f32

    void* args[] = { (void*)&x, (void*)&lengths, (void*)&mask, (void*)&out };
    cudaLaunchCooperativeKernel((void*)pool_kernel,
                                dim3(BB * SS), dim3(128), args, 0, 0);
}